// round 13
// baseline (speedup 1.0000x reference)
#include <cuda_runtime.h>

#define NNODES 100000
#define NEDGES 1600000
#define D 128
#define C 40

// ---------------- scratch (no allocs allowed) ----------------
__device__ float g_msg1[NNODES * D];     // layer-1 aggregated (mean) features
__device__ float g_h[NNODES * D];        // layer-1 output (post relu)
__device__ float g_yl[NNODES * C];       // h @ Wl2^T  (pre-aggregation messages)
__device__ int   g_src[NEDGES];          // decoded + clamped edge sources
__device__ int   g_dst[NEDGES];          // decoded + clamped edge dests
__device__ int   g_deg[NNODES];
__device__ int   g_rowstart[NNODES + 1]; // CSR row offsets (by dst)
__device__ int   g_cursor[NNODES];       // fill cursors
__device__ int   g_csrc[NEDGES];         // CSR column (src) indices
__device__ int   g_is64;                 // edge_index dtype flag

// ---------------- dtype probe: are the first 512 int64 words plausible node ids? ----------------
// Reads 4KB — in-bounds whether the buffer holds 3.2M int64 or 3.2M int32.
__global__ void detect_kernel(const void* eiv) {
    __shared__ int ok;
    if (threadIdx.x == 0) ok = 1;
    __syncthreads();
    const long long* p = (const long long*)eiv;
    for (int k = threadIdx.x; k < 512; k += blockDim.x) {
        long long v = p[k];
        if (v < 0 || v >= NNODES) ok = 0;   // benign race: all writers store 0
    }
    __syncthreads();
    if (threadIdx.x == 0) g_is64 = ok;
}

// ---------------- decode edge list under detected dtype; clamp for hard safety ----------------
__global__ void convert_kernel(const void* eiv) {
    int e = blockIdx.x * blockDim.x + threadIdx.x;
    if (e >= NEDGES) return;
    int s, d;
    if (g_is64) {
        const long long* p = (const long long*)eiv;
        s = (int)p[e];
        d = (int)p[NEDGES + e];
    } else {
        const int* p = (const int*)eiv;
        s = p[e];
        d = p[NEDGES + e];
    }
    s = min(max(s, 0), NNODES - 1);
    d = min(max(d, 0), NNODES - 1);
    g_src[e] = s;
    g_dst[e] = d;
}

// ---------------- zero deg ----------------
__global__ void zero_deg_kernel() {
    int i = blockIdx.x * blockDim.x + threadIdx.x;
    if (i < NNODES) g_deg[i] = 0;
}

// ---------------- degree histogram ----------------
__global__ void deg_kernel() {
    int e = blockIdx.x * blockDim.x + threadIdx.x;
    if (e < NEDGES)
        atomicAdd(&g_deg[g_dst[e]], 1);
}

// ---------------- exclusive scan of deg -> rowstart, cursor (1 block) ----------------
__global__ void scan_kernel() {
    __shared__ int partial[1024];
    int t = threadIdx.x;
    const int chunk = (NNODES + 1023) / 1024;   // 98
    int begin = t * chunk;
    int end = begin + chunk; if (end > NNODES) end = NNODES;
    if (begin > NNODES) begin = NNODES;
    int s = 0;
    for (int i = begin; i < end; i++) s += g_deg[i];
    partial[t] = s;
    __syncthreads();
    // Hillis-Steele inclusive scan over 1024 partials
    for (int off = 1; off < 1024; off <<= 1) {
        int v = (t >= off) ? partial[t - off] : 0;
        __syncthreads();
        partial[t] += v;
        __syncthreads();
    }
    int base = (t == 0) ? 0 : partial[t - 1];
    for (int i = begin; i < end; i++) {
        g_rowstart[i] = base;
        g_cursor[i]   = base;
        base += g_deg[i];
    }
    if (t == 0) g_rowstart[NNODES] = partial[1023];
}

// ---------------- CSR fill: bucket src by dst ----------------
__global__ void fill_kernel() {
    int e = blockIdx.x * blockDim.x + threadIdx.x;
    if (e < NEDGES) {
        int pos = atomicAdd(&g_cursor[g_dst[e]], 1);
        g_csrc[pos] = g_src[e];
    }
}

// ---------------- gather1: g_msg1[i] = mean over neighbors of x[src] ----------------
// One warp per dst node; 32 lanes cover the 128-float row as float4s.
__global__ void gather1_kernel(const float* __restrict__ x) {
    int w = (blockIdx.x * blockDim.x + threadIdx.x) >> 5;
    if (w >= NNODES) return;
    int lane = threadIdx.x & 31;
    int beg = g_rowstart[w];
    int end = g_rowstart[w + 1];
    float4 acc = make_float4(0.f, 0.f, 0.f, 0.f);
    int j = beg;
    for (; j + 1 < end; j += 2) {           // 2-way MLP
        int s0 = g_csrc[j];
        int s1 = g_csrc[j + 1];
        float4 v0 = *reinterpret_cast<const float4*>(&x[(size_t)s0 * D + lane * 4]);
        float4 v1 = *reinterpret_cast<const float4*>(&x[(size_t)s1 * D + lane * 4]);
        acc.x += v0.x + v1.x; acc.y += v0.y + v1.y;
        acc.z += v0.z + v1.z; acc.w += v0.w + v1.w;
    }
    if (j < end) {
        int s0 = g_csrc[j];
        float4 v0 = *reinterpret_cast<const float4*>(&x[(size_t)s0 * D + lane * 4]);
        acc.x += v0.x; acc.y += v0.y; acc.z += v0.z; acc.w += v0.w;
    }
    float sc = 1.0f / fmaxf((float)(end - beg), 1.0f);
    acc.x *= sc; acc.y *= sc; acc.z *= sc; acc.w *= sc;
    *reinterpret_cast<float4*>(&g_msg1[(size_t)w * D + lane * 4]) = acc;
}

// ---------------- fused layer-1 GEMM: h = relu(msg1@Wl1^T + x@Wr1^T + bl1) ----------------
// 512 threads; block tile 64 rows x 128 cols; thread tile 4x4; W transposed in smem.
__global__ __launch_bounds__(512, 1)
void gemm1_kernel(const float* __restrict__ x,
                  const float* __restrict__ Wl,
                  const float* __restrict__ bl,
                  const float* __restrict__ Wr) {
    extern __shared__ float sm[];
    float* Wlt   = sm;                 // [128][128], Wlt[k*128+j] = Wl[j*128+k]
    float* Wrt   = sm + D * D;
    float* a_msg = sm + 2 * D * D;     // [64][128]
    float* a_x   = a_msg + 64 * D;

    int tid = threadIdx.x;
    for (int idx = tid; idx < D * D; idx += 512) {
        int k = idx >> 7, j = idx & 127;
        Wlt[idx] = Wl[j * D + k];
        Wrt[idx] = Wr[j * D + k];
    }
    __syncthreads();

    int colgrp = tid & 31;          // 32 col groups * 4 cols
    int rowgrp = tid >> 5;          // 16 row groups * 4 rows
    int j0 = colgrp * 4;
    int r0 = rowgrp * 4;
    float4 bias = *reinterpret_cast<const float4*>(&bl[j0]);

    const int ntiles = (NNODES + 63) / 64;
    for (int tile = blockIdx.x; tile < ntiles; tile += gridDim.x) {
        int row0 = tile * 64;
        for (int idx = tid; idx < 64 * (D / 4); idx += 512) {
            int r = idx >> 5;       // D/4 = 32 float4 per row
            int cc = idx & 31;
            int grow = row0 + r;
            float4 vm, vx;
            if (grow < NNODES) {
                vm = reinterpret_cast<const float4*>(g_msg1)[grow * 32 + cc];
                vx = reinterpret_cast<const float4*>(x)[grow * 32 + cc];
            } else {
                vm = vx = make_float4(0.f, 0.f, 0.f, 0.f);
            }
            reinterpret_cast<float4*>(a_msg)[idx] = vm;
            reinterpret_cast<float4*>(a_x)[idx]   = vx;
        }
        __syncthreads();

        float acc[4][4];
        #pragma unroll
        for (int i = 0; i < 4; i++)
            #pragma unroll
            for (int jj = 0; jj < 4; jj++) acc[i][jj] = 0.f;

        #pragma unroll 2
        for (int k = 0; k < D; k += 4) {
            float4 am[4], axv[4];
            #pragma unroll
            for (int i = 0; i < 4; i++) {
                am[i]  = *reinterpret_cast<const float4*>(&a_msg[(r0 + i) * D + k]);
                axv[i] = *reinterpret_cast<const float4*>(&a_x[(r0 + i) * D + k]);
            }
            #pragma unroll
            for (int kk = 0; kk < 4; kk++) {
                float4 wl = *reinterpret_cast<const float4*>(&Wlt[(k + kk) * D + j0]);
                float4 wr = *reinterpret_cast<const float4*>(&Wrt[(k + kk) * D + j0]);
                #pragma unroll
                for (int i = 0; i < 4; i++) {
                    float amv = (kk == 0) ? am[i].x : (kk == 1) ? am[i].y : (kk == 2) ? am[i].z : am[i].w;
                    float axs = (kk == 0) ? axv[i].x : (kk == 1) ? axv[i].y : (kk == 2) ? axv[i].z : axv[i].w;
                    acc[i][0] += amv * wl.x + axs * wr.x;
                    acc[i][1] += amv * wl.y + axs * wr.y;
                    acc[i][2] += amv * wl.z + axs * wr.z;
                    acc[i][3] += amv * wl.w + axs * wr.w;
                }
            }
        }

        #pragma unroll
        for (int i = 0; i < 4; i++) {
            int grow = row0 + r0 + i;
            if (grow < NNODES) {
                float4 o;
                o.x = fmaxf(acc[i][0] + bias.x, 0.f);
                o.y = fmaxf(acc[i][1] + bias.y, 0.f);
                o.z = fmaxf(acc[i][2] + bias.z, 0.f);
                o.w = fmaxf(acc[i][3] + bias.w, 0.f);
                *reinterpret_cast<float4*>(&g_h[grow * D + j0]) = o;
            }
        }
        __syncthreads();
    }
}

// ---------------- layer-2 transforms: yl = h@Wl2^T ; out = h@Wr2^T + bl2 ----------------
#define HS_STRIDE 132
__global__ __launch_bounds__(512, 2)
void gemm2_kernel(const float* __restrict__ Wl2,
                  const float* __restrict__ bl2,
                  const float* __restrict__ Wr2,
                  float* __restrict__ out) {
    extern __shared__ float sm[];
    float* Wt = sm;                  // [128][80]  Wt[k*80+c]
    float* hs = sm + D * 80;         // [64][HS_STRIDE]

    int tid = threadIdx.x;
    for (int idx = tid; idx < D * 80; idx += 512) {
        int k = idx / 80, c = idx % 80;
        Wt[idx] = (c < C) ? Wl2[c * D + k] : Wr2[(c - C) * D + k];
    }
    __syncthreads();

    int colgrp = tid & 15;     // 16 groups * 5 cols = 80
    int rowgrp = tid >> 4;     // 32 groups * 2 rows = 64
    int c0 = colgrp * 5;
    int r0 = rowgrp * 2;

    const int ntiles = (NNODES + 63) / 64;
    for (int tile = blockIdx.x; tile < ntiles; tile += gridDim.x) {
        int row0 = tile * 64;
        for (int idx = tid; idx < 64 * (D / 4); idx += 512) {
            int r = idx >> 5, cc = idx & 31;
            float4 v = (row0 + r < NNODES)
                ? reinterpret_cast<const float4*>(g_h)[(row0 + r) * 32 + cc]
                : make_float4(0.f, 0.f, 0.f, 0.f);
            *reinterpret_cast<float4*>(&hs[r * HS_STRIDE + cc * 4]) = v;
        }
        __syncthreads();

        float acc0[5], acc1[5];
        #pragma unroll
        for (int q = 0; q < 5; q++) { acc0[q] = 0.f; acc1[q] = 0.f; }

        #pragma unroll 2
        for (int k = 0; k < D; k += 4) {
            float4 a0 = *reinterpret_cast<const float4*>(&hs[r0 * HS_STRIDE + k]);
            float4 a1 = *reinterpret_cast<const float4*>(&hs[(r0 + 1) * HS_STRIDE + k]);
            #pragma unroll
            for (int kk = 0; kk < 4; kk++) {
                float av0 = (kk == 0) ? a0.x : (kk == 1) ? a0.y : (kk == 2) ? a0.z : a0.w;
                float av1 = (kk == 0) ? a1.x : (kk == 1) ? a1.y : (kk == 2) ? a1.z : a1.w;
                #pragma unroll
                for (int q = 0; q < 5; q++) {
                    float w = Wt[(k + kk) * 80 + c0 + q];
                    acc0[q] += av0 * w;
                    acc1[q] += av1 * w;
                }
            }
        }

        int grow0 = row0 + r0;
        int grow1 = grow0 + 1;
        #pragma unroll
        for (int q = 0; q < 5; q++) {
            int c = c0 + q;
            if (c < C) {
                if (grow0 < NNODES) g_yl[grow0 * C + c] = acc0[q];
                if (grow1 < NNODES) g_yl[grow1 * C + c] = acc1[q];
            } else {
                int cc = c - C;
                float b = bl2[cc];
                if (grow0 < NNODES) out[grow0 * C + cc] = acc0[q] + b;
                if (grow1 < NNODES) out[grow1 * C + cc] = acc1[q] + b;
            }
        }
        __syncthreads();
    }
}

// ---------------- gather2: out[i] += mean over neighbors of yl[src] ----------------
// One warp per dst node; lanes 0..9 cover the 40-float row as float4s.
__global__ void gather2_kernel(float* __restrict__ out) {
    int w = (blockIdx.x * blockDim.x + threadIdx.x) >> 5;
    if (w >= NNODES) return;
    int lane = threadIdx.x & 31;
    if (lane >= 10) return;
    int beg = g_rowstart[w];
    int end = g_rowstart[w + 1];
    float4 acc = make_float4(0.f, 0.f, 0.f, 0.f);
    int j = beg;
    for (; j + 1 < end; j += 2) {
        int s0 = g_csrc[j];
        int s1 = g_csrc[j + 1];
        float4 v0 = *reinterpret_cast<const float4*>(&g_yl[(size_t)s0 * C + lane * 4]);
        float4 v1 = *reinterpret_cast<const float4*>(&g_yl[(size_t)s1 * C + lane * 4]);
        acc.x += v0.x + v1.x; acc.y += v0.y + v1.y;
        acc.z += v0.z + v1.z; acc.w += v0.w + v1.w;
    }
    if (j < end) {
        int s0 = g_csrc[j];
        float4 v0 = *reinterpret_cast<const float4*>(&g_yl[(size_t)s0 * C + lane * 4]);
        acc.x += v0.x; acc.y += v0.y; acc.z += v0.z; acc.w += v0.w;
    }
    float sc = 1.0f / fmaxf((float)(end - beg), 1.0f);
    float4 o = *reinterpret_cast<float4*>(&out[(size_t)w * C + lane * 4]);
    o.x += acc.x * sc; o.y += acc.y * sc; o.z += acc.z * sc; o.w += acc.w * sc;
    *reinterpret_cast<float4*>(&out[(size_t)w * C + lane * 4]) = o;
}

// ---------------- launch ----------------
extern "C" void kernel_launch(void* const* d_in, const int* in_sizes, int n_in,
                              void* d_out, int out_size) {
    const float* x   = (const float*)d_in[0];
    const void*  ei  = d_in[1];
    const float* Wl1 = (const float*)d_in[2];
    const float* bl1 = (const float*)d_in[3];
    const float* Wr1 = (const float*)d_in[4];
    const float* Wl2 = (const float*)d_in[5];
    const float* bl2 = (const float*)d_in[6];
    const float* Wr2 = (const float*)d_in[7];
    float* out = (float*)d_out;

    const int SMEM1 = (2 * D * D + 2 * 64 * D) * sizeof(float);          // 192 KB
    const int SMEM2 = (D * 80 + 64 * HS_STRIDE) * sizeof(float);         // ~74 KB
    cudaFuncSetAttribute(gemm1_kernel, cudaFuncAttributeMaxDynamicSharedMemorySize, SMEM1);
    cudaFuncSetAttribute(gemm2_kernel, cudaFuncAttributeMaxDynamicSharedMemorySize, SMEM2);

    detect_kernel<<<1, 256>>>(ei);
    convert_kernel<<<(NEDGES + 255) / 256, 256>>>(ei);
    zero_deg_kernel<<<(NNODES + 255) / 256, 256>>>();
    deg_kernel<<<(NEDGES + 255) / 256, 256>>>();
    scan_kernel<<<1, 1024>>>();
    fill_kernel<<<(NEDGES + 255) / 256, 256>>>();
    gather1_kernel<<<(NNODES * 32 + 255) / 256, 256>>>(x);
    gemm1_kernel<<<148, 512, SMEM1>>>(x, Wl1, bl1, Wr1);
    gemm2_kernel<<<296, 512, SMEM2>>>(Wl2, bl2, Wr2, out);
    gather2_kernel<<<(NNODES * 32 + 255) / 256, 256>>>(out);
}

// round 17
// speedup vs baseline: 1.0702x; 1.0702x over previous
#include <cuda_runtime.h>

#define NNODES 100000
#define NEDGES 1600000
#define D 128
#define C 40

// ---------------- scratch (no allocs allowed) ----------------
__device__ float g_msg1[NNODES * D];     // layer-1 aggregated (mean) features
__device__ float g_h[NNODES * D];        // layer-1 output (post relu)
__device__ float g_yl[NNODES * C];       // h @ Wl2^T  (pre-aggregation messages)
__device__ int   g_src[NEDGES];          // decoded + clamped edge sources
__device__ int   g_dst[NEDGES];          // decoded + clamped edge dests
__device__ int   g_deg[NNODES];
__device__ int   g_rowstart[NNODES + 1]; // CSR row offsets (by dst)
__device__ int   g_cursor[NNODES];       // fill cursors
__device__ int   g_csrc[NEDGES];         // CSR column (src) indices
__device__ int   g_is64;                 // edge_index dtype flag

// ---------------- f32x2 packed helpers (Blackwell; forms match ptx_helpers.cuh) ----
__device__ __forceinline__ unsigned long long pack2(float v) {
    unsigned long long r;
    unsigned int b = __float_as_uint(v);
    asm("mov.b64 %0, {%1, %1};" : "=l"(r) : "r"(b));
    return r;
}
__device__ __forceinline__ float2 unpack2(unsigned long long p) {
    unsigned int lo, hi;
    asm("mov.b64 {%0, %1}, %2;" : "=r"(lo), "=r"(hi) : "l"(p));
    return make_float2(__uint_as_float(lo), __uint_as_float(hi));
}
__device__ __forceinline__ void fma2(unsigned long long& d,
                                     unsigned long long a, unsigned long long b) {
    asm("fma.rn.f32x2 %0, %1, %2, %0;" : "+l"(d) : "l"(a), "l"(b));
}

// ---------------- dtype probe: are the first 512 int64 words plausible node ids? ----------------
__global__ void detect_kernel(const void* eiv) {
    __shared__ int ok;
    if (threadIdx.x == 0) ok = 1;
    __syncthreads();
    const long long* p = (const long long*)eiv;
    for (int k = threadIdx.x; k < 512; k += blockDim.x) {
        long long v = p[k];
        if (v < 0 || v >= NNODES) ok = 0;   // benign race: all writers store 0
    }
    __syncthreads();
    if (threadIdx.x == 0) g_is64 = ok;
}

// ---------------- decode edge list under detected dtype; clamp for hard safety ----------------
__global__ void convert_kernel(const void* eiv) {
    int e = blockIdx.x * blockDim.x + threadIdx.x;
    if (e >= NEDGES) return;
    int s, d;
    if (g_is64) {
        const long long* p = (const long long*)eiv;
        s = (int)p[e];
        d = (int)p[NEDGES + e];
    } else {
        const int* p = (const int*)eiv;
        s = p[e];
        d = p[NEDGES + e];
    }
    s = min(max(s, 0), NNODES - 1);
    d = min(max(d, 0), NNODES - 1);
    g_src[e] = s;
    g_dst[e] = d;
}

// ---------------- zero deg ----------------
__global__ void zero_deg_kernel() {
    int i = blockIdx.x * blockDim.x + threadIdx.x;
    if (i < NNODES) g_deg[i] = 0;
}

// ---------------- degree histogram ----------------
__global__ void deg_kernel() {
    int e = blockIdx.x * blockDim.x + threadIdx.x;
    if (e < NEDGES)
        atomicAdd(&g_deg[g_dst[e]], 1);
}

// ---------------- exclusive scan of deg -> rowstart, cursor (1 block) ----------------
__global__ void scan_kernel() {
    __shared__ int partial[1024];
    int t = threadIdx.x;
    const int chunk = (NNODES + 1023) / 1024;   // 98
    int begin = t * chunk;
    int end = begin + chunk; if (end > NNODES) end = NNODES;
    if (begin > NNODES) begin = NNODES;
    int s = 0;
    for (int i = begin; i < end; i++) s += g_deg[i];
    partial[t] = s;
    __syncthreads();
    for (int off = 1; off < 1024; off <<= 1) {
        int v = (t >= off) ? partial[t - off] : 0;
        __syncthreads();
        partial[t] += v;
        __syncthreads();
    }
    int base = (t == 0) ? 0 : partial[t - 1];
    for (int i = begin; i < end; i++) {
        g_rowstart[i] = base;
        g_cursor[i]   = base;
        base += g_deg[i];
    }
    if (t == 0) g_rowstart[NNODES] = partial[1023];
}

// ---------------- CSR fill: bucket src by dst ----------------
__global__ void fill_kernel() {
    int e = blockIdx.x * blockDim.x + threadIdx.x;
    if (e < NEDGES) {
        int pos = atomicAdd(&g_cursor[g_dst[e]], 1);
        g_csrc[pos] = g_src[e];
    }
}

// ---------------- gather1: g_msg1[i] = mean over neighbors of x[src] ----------------
__global__ void gather1_kernel(const float* __restrict__ x) {
    int w = (blockIdx.x * blockDim.x + threadIdx.x) >> 5;
    if (w >= NNODES) return;
    int lane = threadIdx.x & 31;
    int beg = g_rowstart[w];
    int end = g_rowstart[w + 1];
    float4 acc = make_float4(0.f, 0.f, 0.f, 0.f);
    int j = beg;
    for (; j + 1 < end; j += 2) {           // 2-way MLP
        int s0 = g_csrc[j];
        int s1 = g_csrc[j + 1];
        float4 v0 = *reinterpret_cast<const float4*>(&x[(size_t)s0 * D + lane * 4]);
        float4 v1 = *reinterpret_cast<const float4*>(&x[(size_t)s1 * D + lane * 4]);
        acc.x += v0.x + v1.x; acc.y += v0.y + v1.y;
        acc.z += v0.z + v1.z; acc.w += v0.w + v1.w;
    }
    if (j < end) {
        int s0 = g_csrc[j];
        float4 v0 = *reinterpret_cast<const float4*>(&x[(size_t)s0 * D + lane * 4]);
        acc.x += v0.x; acc.y += v0.y; acc.z += v0.z; acc.w += v0.w;
    }
    float sc = 1.0f / fmaxf((float)(end - beg), 1.0f);
    acc.x *= sc; acc.y *= sc; acc.z *= sc; acc.w *= sc;
    *reinterpret_cast<float4*>(&g_msg1[(size_t)w * D + lane * 4]) = acc;
}

// ---------------- fused layer-1 GEMM: h = relu(msg1@Wl1^T + x@Wr1^T + bl1) ----------------
// 256 threads; block tile 128 rows x 128 cols; thread tile 8x8; f32x2 packed FMA.
// Two sequential passes (msg1*Wl, x*Wr) share one 64KB A-tile buffer.
__global__ __launch_bounds__(256, 1)
void gemm1_kernel(const float* __restrict__ x,
                  const float* __restrict__ Wl,
                  const float* __restrict__ bl,
                  const float* __restrict__ Wr) {
    extern __shared__ float sm[];
    float* Wlt  = sm;                  // [128][128], Wlt[k*128+j] = Wl[j*128+k]
    float* Wrt  = sm + D * D;
    float* abuf = sm + 2 * D * D;      // [128][128] staging for msg1/x tile

    int tid = threadIdx.x;
    for (int idx = tid; idx < D * D; idx += 256) {
        int k = idx >> 7, j = idx & 127;
        Wlt[idx] = Wl[j * D + k];
        Wrt[idx] = Wr[j * D + k];
    }

    int colgrp = tid & 15;          // 16 col groups * 8 cols
    int rowgrp = tid >> 4;          // 16 row groups * 8 rows
    int j0 = colgrp * 8;
    int r0 = rowgrp * 8;

    float4 b0 = *reinterpret_cast<const float4*>(&bl[j0]);
    float4 b1 = *reinterpret_cast<const float4*>(&bl[j0 + 4]);

    const int ntiles = (NNODES + 127) / 128;
    for (int tile = blockIdx.x; tile < ntiles; tile += gridDim.x) {
        int row0 = tile * 128;

        unsigned long long acc[8][4];
        #pragma unroll
        for (int i = 0; i < 8; i++)
            #pragma unroll
            for (int p = 0; p < 4; p++) acc[i][p] = 0ULL;

        for (int pass = 0; pass < 2; pass++) {
            __syncthreads();   // protect prior reads of abuf (and weight staging on entry)
            const float* A = (pass == 0) ? (const float*)g_msg1 : x;
            for (int idx = tid; idx < 128 * 32; idx += 256) {
                int r = idx >> 5, cc = idx & 31;
                int grow = row0 + r;
                float4 v = (grow < NNODES)
                    ? reinterpret_cast<const float4*>(A)[(size_t)grow * 32 + cc]
                    : make_float4(0.f, 0.f, 0.f, 0.f);
                reinterpret_cast<float4*>(abuf)[idx] = v;
            }
            __syncthreads();
            const float* Wt = (pass == 0) ? Wlt : Wrt;

            #pragma unroll 2
            for (int k4 = 0; k4 < D; k4 += 4) {
                float4 a[8];
                #pragma unroll
                for (int i = 0; i < 8; i++)
                    a[i] = *reinterpret_cast<const float4*>(&abuf[(r0 + i) * D + k4]);
                #pragma unroll
                for (int kk = 0; kk < 4; kk++) {
                    const unsigned long long* wp =
                        reinterpret_cast<const unsigned long long*>(&Wt[(k4 + kk) * D + j0]);
                    unsigned long long w0 = wp[0], w1 = wp[1], w2 = wp[2], w3 = wp[3];
                    #pragma unroll
                    for (int i = 0; i < 8; i++) {
                        float av = (kk == 0) ? a[i].x : (kk == 1) ? a[i].y
                                 : (kk == 2) ? a[i].z : a[i].w;
                        unsigned long long av2 = pack2(av);
                        fma2(acc[i][0], av2, w0);
                        fma2(acc[i][1], av2, w1);
                        fma2(acc[i][2], av2, w2);
                        fma2(acc[i][3], av2, w3);
                    }
                }
            }
        }

        #pragma unroll
        for (int i = 0; i < 8; i++) {
            int grow = row0 + r0 + i;
            if (grow < NNODES) {
                float2 p0 = unpack2(acc[i][0]);
                float2 p1 = unpack2(acc[i][1]);
                float2 p2 = unpack2(acc[i][2]);
                float2 p3 = unpack2(acc[i][3]);
                float4 o0 = make_float4(fmaxf(p0.x + b0.x, 0.f), fmaxf(p0.y + b0.y, 0.f),
                                        fmaxf(p1.x + b0.z, 0.f), fmaxf(p1.y + b0.w, 0.f));
                float4 o1 = make_float4(fmaxf(p2.x + b1.x, 0.f), fmaxf(p2.y + b1.y, 0.f),
                                        fmaxf(p3.x + b1.z, 0.f), fmaxf(p3.y + b1.w, 0.f));
                *reinterpret_cast<float4*>(&g_h[(size_t)grow * D + j0])     = o0;
                *reinterpret_cast<float4*>(&g_h[(size_t)grow * D + j0 + 4]) = o1;
            }
        }
    }
}

// ---------------- layer-2 transforms: yl = h@Wl2^T ; out = h@Wr2^T + bl2 ----------------
#define HS_STRIDE 132
__global__ __launch_bounds__(512, 2)
void gemm2_kernel(const float* __restrict__ Wl2,
                  const float* __restrict__ bl2,
                  const float* __restrict__ Wr2,
                  float* __restrict__ out) {
    extern __shared__ float sm[];
    float* Wt = sm;                  // [128][80]  Wt[k*80+c]
    float* hs = sm + D * 80;         // [64][HS_STRIDE]

    int tid = threadIdx.x;
    for (int idx = tid; idx < D * 80; idx += 512) {
        int k = idx / 80, c = idx % 80;
        Wt[idx] = (c < C) ? Wl2[c * D + k] : Wr2[(c - C) * D + k];
    }
    __syncthreads();

    int colgrp = tid & 15;     // 16 groups * 5 cols = 80
    int rowgrp = tid >> 4;     // 32 groups * 2 rows = 64
    int c0 = colgrp * 5;
    int r0 = rowgrp * 2;

    const int ntiles = (NNODES + 63) / 64;
    for (int tile = blockIdx.x; tile < ntiles; tile += gridDim.x) {
        int row0 = tile * 64;
        for (int idx = tid; idx < 64 * (D / 4); idx += 512) {
            int r = idx >> 5, cc = idx & 31;
            float4 v = (row0 + r < NNODES)
                ? reinterpret_cast<const float4*>(g_h)[(row0 + r) * 32 + cc]
                : make_float4(0.f, 0.f, 0.f, 0.f);
            *reinterpret_cast<float4*>(&hs[r * HS_STRIDE + cc * 4]) = v;
        }
        __syncthreads();

        float acc0[5], acc1[5];
        #pragma unroll
        for (int q = 0; q < 5; q++) { acc0[q] = 0.f; acc1[q] = 0.f; }

        #pragma unroll 2
        for (int k = 0; k < D; k += 4) {
            float4 a0 = *reinterpret_cast<const float4*>(&hs[r0 * HS_STRIDE + k]);
            float4 a1 = *reinterpret_cast<const float4*>(&hs[(r0 + 1) * HS_STRIDE + k]);
            #pragma unroll
            for (int kk = 0; kk < 4; kk++) {
                float av0 = (kk == 0) ? a0.x : (kk == 1) ? a0.y : (kk == 2) ? a0.z : a0.w;
                float av1 = (kk == 0) ? a1.x : (kk == 1) ? a1.y : (kk == 2) ? a1.z : a1.w;
                #pragma unroll
                for (int q = 0; q < 5; q++) {
                    float w = Wt[(k + kk) * 80 + c0 + q];
                    acc0[q] += av0 * w;
                    acc1[q] += av1 * w;
                }
            }
        }

        int grow0 = row0 + r0;
        int grow1 = grow0 + 1;
        #pragma unroll
        for (int q = 0; q < 5; q++) {
            int c = c0 + q;
            if (c < C) {
                if (grow0 < NNODES) g_yl[grow0 * C + c] = acc0[q];
                if (grow1 < NNODES) g_yl[grow1 * C + c] = acc1[q];
            } else {
                int cc = c - C;
                float b = bl2[cc];
                if (grow0 < NNODES) out[grow0 * C + cc] = acc0[q] + b;
                if (grow1 < NNODES) out[grow1 * C + cc] = acc1[q] + b;
            }
        }
        __syncthreads();
    }
}

// ---------------- gather2: out[i] += mean over neighbors of yl[src] ----------------
__global__ void gather2_kernel(float* __restrict__ out) {
    int w = (blockIdx.x * blockDim.x + threadIdx.x) >> 5;
    if (w >= NNODES) return;
    int lane = threadIdx.x & 31;
    if (lane >= 10) return;
    int beg = g_rowstart[w];
    int end = g_rowstart[w + 1];
    float4 acc = make_float4(0.f, 0.f, 0.f, 0.f);
    int j = beg;
    for (; j + 1 < end; j += 2) {
        int s0 = g_csrc[j];
        int s1 = g_csrc[j + 1];
        float4 v0 = *reinterpret_cast<const float4*>(&g_yl[(size_t)s0 * C + lane * 4]);
        float4 v1 = *reinterpret_cast<const float4*>(&g_yl[(size_t)s1 * C + lane * 4]);
        acc.x += v0.x + v1.x; acc.y += v0.y + v1.y;
        acc.z += v0.z + v1.z; acc.w += v0.w + v1.w;
    }
    if (j < end) {
        int s0 = g_csrc[j];
        float4 v0 = *reinterpret_cast<const float4*>(&g_yl[(size_t)s0 * C + lane * 4]);
        acc.x += v0.x; acc.y += v0.y; acc.z += v0.z; acc.w += v0.w;
    }
    float sc = 1.0f / fmaxf((float)(end - beg), 1.0f);
    float4 o = *reinterpret_cast<float4*>(&out[(size_t)w * C + lane * 4]);
    o.x += acc.x * sc; o.y += acc.y * sc; o.z += acc.z * sc; o.w += acc.w * sc;
    *reinterpret_cast<float4*>(&out[(size_t)w * C + lane * 4]) = o;
}

// ---------------- launch ----------------
extern "C" void kernel_launch(void* const* d_in, const int* in_sizes, int n_in,
                              void* d_out, int out_size) {
    const float* x   = (const float*)d_in[0];
    const void*  ei  = d_in[1];
    const float* Wl1 = (const float*)d_in[2];
    const float* bl1 = (const float*)d_in[3];
    const float* Wr1 = (const float*)d_in[4];
    const float* Wl2 = (const float*)d_in[5];
    const float* bl2 = (const float*)d_in[6];
    const float* Wr2 = (const float*)d_in[7];
    float* out = (float*)d_out;

    const int SMEM1 = 3 * D * D * sizeof(float);                         // 192 KB
    const int SMEM2 = (D * 80 + 64 * HS_STRIDE) * sizeof(float);         // ~74 KB
    cudaFuncSetAttribute(gemm1_kernel, cudaFuncAttributeMaxDynamicSharedMemorySize, SMEM1);
    cudaFuncSetAttribute(gemm2_kernel, cudaFuncAttributeMaxDynamicSharedMemorySize, SMEM2);

    detect_kernel<<<1, 256>>>(ei);
    convert_kernel<<<(NEDGES + 255) / 256, 256>>>(ei);
    zero_deg_kernel<<<(NNODES + 255) / 256, 256>>>();
    deg_kernel<<<(NEDGES + 255) / 256, 256>>>();
    scan_kernel<<<1, 1024>>>();
    fill_kernel<<<(NEDGES + 255) / 256, 256>>>();
    gather1_kernel<<<(NNODES * 32 + 255) / 256, 256>>>(x);
    gemm1_kernel<<<148, 256, SMEM1>>>(x, Wl1, bl1, Wr1);
    gemm2_kernel<<<296, 512, SMEM2>>>(Wl2, bl2, Wr2, out);
    gather2_kernel<<<(NNODES * 32 + 255) / 256, 256>>>(out);
}